// round 15
// baseline (speedup 1.0000x reference)
#include <cuda_runtime.h>
#include <cuda_fp16.h>
#include <cstdint>
#include <float.h>

#define FEAT 128
#define MAXN 50000
#define MAXE 600000
#define CAP 96

// ---------------- scratch -------------------------------------------------
__device__ __half g_Ch[MAXN * FEAT];      // theta(x) fp16 (gather reads)
__device__ __half g_Dh[MAXN * FEAT];      // phi - theta + (tb+pb), fp16
__device__ __half g_Xf[MAXN * FEAT];      // current X, fp16
__device__ __half g_Wf[4 * 256 * 128];    // [l][row<128:theta else phi][k]
__device__ int g_cur[MAXN];   // bucket fill count == degree (zero-init at load;
                              // re-zeroed by gather layer 3 for the next run)
__device__ int g_csr[MAXN * CAP];         // premultiplied src*32, bucketed by dst

// ------- fused setup: convert X and W to fp16 + bucket scatter --------------
__global__ void setup_kernel(const float* __restrict__ x,
                             const float* __restrict__ tw,
                             const float* __restrict__ pw,
                             const int* __restrict__ src,
                             const int* __restrict__ dst,
                             int n, int e) {
    int i = blockIdx.x * blockDim.x + threadIdx.x;
    if (i < e) {
        int d = dst[i];
        int p = atomicAdd(&g_cur[d], 1);
        g_csr[d * CAP + p] = src[i] * 32;   // premultiplied uint2-row index
    }
    if (i < 4 * 256 * 128) {
        int l = i >> 15;
        int r = (i >> 7) & 255;
        int k = i & 127;
        const float* W = (r < 128) ? tw : pw;
        g_Wf[i] = __float2half_rn(W[(size_t)l * FEAT * FEAT + (size_t)(r & 127) * FEAT + k]);
    }
    if (i < n * FEAT) {
        g_Xf[i] = __float2half_rn(x[i]);
    }
}

// ------- persistent mma.sync fp16 GEMM: BM=96, 768 thr, theta/phi split -----
// 24 warps: warp_m = wid>>3 (3x32 rows), warp_n = (wid>>1)&3 (4x32 cols),
// tp = wid&1 (0=theta, 1=phi). Each warp: one 32x32 block, 32 f32 accums.
// Smem: W[256 x 272B] @0, A dbl buf [2][96 x 272B], epi exchange 48KB.
#define WROW 272
#define SM_W_BYTES (256 * WROW)
#define SM_A_OFF SM_W_BYTES
#define SM_A_BYTES (96 * WROW)
#define SM_EPI_OFF (SM_W_BYTES + 2 * SM_A_BYTES)
#define GEMM_SMEM (SM_EPI_OFF + 12 * 4096)

__device__ __forceinline__ uint32_t smem_u32(const void* p) {
    uint32_t a;
    asm("{ .reg .u64 t; cvta.to.shared.u64 t, %1; cvt.u32.u64 %0, t; }" : "=r"(a) : "l"(p));
    return a;
}
__device__ __forceinline__ uint64_t gmem_u64(const void* p) {
    uint64_t a;
    asm("cvta.to.global.u64 %0, %1;" : "=l"(a) : "l"(p));
    return a;
}
#define CP_ASYNC16(dst, src, sz)                                             \
    asm volatile("cp.async.cg.shared.global [%0], [%1], 16, %2;"             \
                 :: "r"(dst), "l"(src), "r"(sz) : "memory")
#define CP_COMMIT() asm volatile("cp.async.commit_group;" ::: "memory")
#define CP_WAIT0() asm volatile("cp.async.wait_group 0;" ::: "memory")

#define LDMX4(r0, r1, r2, r3, addr)                                          \
    asm volatile("ldmatrix.sync.aligned.m8n8.x4.shared.b16 {%0,%1,%2,%3}, [%4];" \
                 : "=r"(r0), "=r"(r1), "=r"(r2), "=r"(r3) : "r"(addr))
#define MMA16816F(d, a0, a1, a2, a3, b0, b1)                                 \
    asm volatile("mma.sync.aligned.m16n8k16.row.col.f32.f16.f16.f32 "        \
                 "{%0,%1,%2,%3},{%4,%5,%6,%7},{%8,%9},{%0,%1,%2,%3};"        \
                 : "+f"((d)[0]), "+f"((d)[1]), "+f"((d)[2]), "+f"((d)[3])    \
                 : "r"(a0), "r"(a1), "r"(a2), "r"(a3), "r"(b0), "r"(b1))

__global__ void __launch_bounds__(768, 1)
gemm_mma_kernel(int layer, const float* __restrict__ tb,
                const float* __restrict__ pb, int n, int ntiles) {
    extern __shared__ __half sm[];
    uint32_t smb = smem_u32(sm);
    int t = threadIdx.x, lane = t & 31, wid = t >> 5;

    uint64_t Wg = gmem_u64(g_Wf + (size_t)layer * 32768);
    uint64_t Xg = gmem_u64(g_Xf);

    int tp     = wid & 1;          // 0 = theta, 1 = phi
    int warp_n = (wid >> 1) & 3;   // 4 n-warps x 32 cols
    int warp_m = wid >> 3;         // 3 m-warps x 32 rows
    int pair   = wid >> 1;         // theta/phi pair id (0..11)

    // ---- prologue: load W once (4096 x 16B chunks) ----
    #pragma unroll
    for (int j = 0; j < 6; j++) {
        int i = t + j * 768;
        if (i < 4096) {
            int row = i >> 4, q = i & 15;
            CP_ASYNC16(smb + (uint32_t)(row * WROW + q * 16),
                       Wg + (uint64_t)(row * 256 + q * 16), 16u);
        }
    }
    CP_COMMIT();

    // A loader: 96 rows x 256B = 1536 x 16B chunks, 2 per thread
    auto issue_A = [&](int tile, int buf) {
        int m0 = tile * 96;
        uint32_t stA = smb + SM_A_OFF + (uint32_t)buf * SM_A_BYTES;
        #pragma unroll
        for (int j = 0; j < 2; j++) {
            int i = t + j * 768;
            int row = i >> 4, q = i & 15;
            int gr = m0 + row;
            uint32_t ok = (gr < n) ? 16u : 0u;
            CP_ASYNC16(stA + (uint32_t)(row * WROW + q * 16),
                       Xg + ((uint64_t)(uint32_t)gr * 256 + q * 16), ok);
        }
        CP_COMMIT();
    };

    int tile = blockIdx.x;
    if (tile < ntiles) issue_A(tile, 0);

    // ldmatrix lane maps
    int lr  = (lane & 7) + ((lane >> 3) & 1) * 8;
    int lk8 = (lane >> 4) * 8;
    int bg  = lane >> 3;
    int br_ = (lane & 7) + ((bg >> 1) & 1) * 8;
    int bk8 = (bg & 1) * 8;

    int brow_base = tp * 128 + warp_n * 32;   // B rows for this warp

    int buf = 0;
    for (; tile < ntiles; tile += gridDim.x, buf ^= 1) {
        int m0 = tile * 96;

        CP_WAIT0();
        __syncthreads();

        int ntile = tile + gridDim.x;
        if (ntile < ntiles) issue_A(ntile, buf ^ 1);

        float acc[2][4][4];
        #pragma unroll
        for (int mt = 0; mt < 2; mt++)
            #pragma unroll
            for (int nt = 0; nt < 4; nt++)
                #pragma unroll
                for (int r = 0; r < 4; r++) acc[mt][nt][r] = 0.f;

        uint32_t stA = smb + SM_A_OFF + (uint32_t)buf * SM_A_BYTES;

        #pragma unroll
        for (int ks = 0; ks < 8; ks++) {
            int k = ks * 16;
            uint32_t aF[2][4];
            #pragma unroll
            for (int mt = 0; mt < 2; mt++) {
                uint32_t ad = stA + (uint32_t)((warp_m * 32 + mt * 16 + lr) * WROW + (k + lk8) * 2);
                LDMX4(aF[mt][0], aF[mt][1], aF[mt][2], aF[mt][3], ad);
            }
            uint32_t bF[4][2];
            #pragma unroll
            for (int nh = 0; nh < 2; nh++) {
                uint32_t bd = smb + (uint32_t)((brow_base + nh * 16 + br_) * WROW + (k + bk8) * 2);
                LDMX4(bF[nh * 2][0], bF[nh * 2][1], bF[nh * 2 + 1][0], bF[nh * 2 + 1][1], bd);
            }
            #pragma unroll
            for (int mt = 0; mt < 2; mt++)
                #pragma unroll
                for (int nt = 0; nt < 4; nt++)
                    MMA16816F(acc[mt][nt], aF[mt][0], aF[mt][1], aF[mt][2], aF[mt][3],
                              bF[nt][0], bF[nt][1]);
        }

        // ---- epilogue: phi warps stage acc through smem; theta warps emit --
        float* epi = (float*)((char*)sm + SM_EPI_OFF + pair * 4096);
        if (tp == 1) {
            #pragma unroll
            for (int mt = 0; mt < 2; mt++)
                #pragma unroll
                for (int nt = 0; nt < 4; nt++)
                    *(float4*)(epi + (mt * 4 + nt) * 128 + lane * 4) =
                        *(float4*)acc[mt][nt];
        }
        __syncthreads();
        if (tp == 0) {
            #pragma unroll
            for (int mt = 0; mt < 2; mt++) {
                #pragma unroll
                for (int nt = 0; nt < 4; nt++) {
                    float4 pv = *(float4*)(epi + (mt * 4 + nt) * 128 + lane * 4);
                    int f = warp_n * 32 + nt * 8 + (lane & 3) * 2;
                    float bias0 = __ldg(&tb[f]) + __ldg(&pb[f]);
                    float bias1 = __ldg(&tb[f + 1]) + __ldg(&pb[f + 1]);
                    int m = m0 + warp_m * 32 + mt * 16 + (lane >> 2);
                    float* c = acc[mt][nt];
                    if (m < n) {
                        *(__half2*)(g_Ch + (size_t)m * FEAT + f) = __floats2half2_rn(c[0], c[1]);
                        *(__half2*)(g_Dh + (size_t)m * FEAT + f) =
                            __floats2half2_rn(pv.x - c[0] + bias0, pv.y - c[1] + bias1);
                    }
                    if (m + 8 < n) {
                        *(__half2*)(g_Ch + (size_t)(m + 8) * FEAT + f) = __floats2half2_rn(c[2], c[3]);
                        *(__half2*)(g_Dh + (size_t)(m + 8) * FEAT + f) =
                            __floats2half2_rn(pv.z - c[2] + bias0, pv.w - c[3] + bias1);
                    }
                }
            }
        }
    }
}

// ---------------- gather-max: 1 warp/node, uint2, MLP=2 (R11 exact) --------
__device__ __forceinline__ uint32_t hmax2u(uint32_t x, uint32_t y) {
    __half2 r = __hmax2(*(__half2*)&x, *(__half2*)&y);
    return *(uint32_t*)&r;
}

__global__ void gather_kernel(float* __restrict__ dout, int layer, int n) {
    int gw = (blockIdx.x * blockDim.x + threadIdx.x) >> 5;
    int lane = threadIdx.x & 31;
    if (gw >= n) return;

    int deg = g_cur[gw];
    const int* lst = g_csr + gw * CAP;
    const uint2* C2 = (const uint2*)g_Ch;

    // hoisted D load (independent of edge loop)
    uint2 dv = __ldg(&((const uint2*)g_Dh)[(size_t)gw * 32 + lane]);

    const uint32_t NEG = 0xFBFFFBFFu;  // -65504 x2
    uint32_t a0 = NEG, a1 = NEG, b0 = NEG, b1 = NEG;

    int e = 0;
    for (; e + 1 < deg; e += 2) {
        int s0 = __ldg(&lst[e]);          // premultiplied src*32
        int s1 = __ldg(&lst[e + 1]);
        uint2 v0 = __ldg(&C2[(size_t)(uint32_t)(s0 + lane)]);
        uint2 v1 = __ldg(&C2[(size_t)(uint32_t)(s1 + lane)]);
        a0 = hmax2u(a0, v0.x); a1 = hmax2u(a1, v0.y);
        b0 = hmax2u(b0, v1.x); b1 = hmax2u(b1, v1.y);
    }
    if (e < deg) {
        int s0 = __ldg(&lst[e]);
        uint2 v0 = __ldg(&C2[(size_t)(uint32_t)(s0 + lane)]);
        a0 = hmax2u(a0, v0.x); a1 = hmax2u(a1, v0.y);
    }
    a0 = hmax2u(a0, b0);
    a1 = hmax2u(a1, b1);

    float2 m01 = __half22float2(*(__half2*)&a0);
    float2 m23 = __half22float2(*(__half2*)&a1);
    float2 d01 = __half22float2(*(__half2*)&dv.x);
    float2 d23 = __half22float2(*(__half2*)&dv.y);

    float4 o;
    o.x = fmaxf(0.f, d01.x + m01.x);
    o.y = fmaxf(0.f, d01.y + m01.y);
    o.z = fmaxf(0.f, d23.x + m23.x);
    o.w = fmaxf(0.f, d23.y + m23.y);

    if (layer == 3) {
        ((float4*)dout)[(size_t)gw * 32 + lane] = o;
        if (lane == 0) g_cur[gw] = 0;     // re-arm bucket counters for next run
    } else {
        __half2 p0 = __floats2half2_rn(o.x, o.y);
        __half2 p1 = __floats2half2_rn(o.z, o.w);
        uint2 xv;
        xv.x = *(uint32_t*)&p0;
        xv.y = *(uint32_t*)&p1;
        *(uint2*)(g_Xf + (size_t)gw * FEAT + lane * 4) = xv;
    }
}

// ---------------- launch ----------------------------------------------------
extern "C" void kernel_launch(void* const* d_in, const int* in_sizes, int n_in,
                              void* d_out, int out_size) {
    const float* feats = (const float*)d_in[0];
    const int*   src   = (const int*)d_in[1];
    const int*   dst   = (const int*)d_in[2];
    const float* tw    = (const float*)d_in[3];
    const float* tb    = (const float*)d_in[4];
    const float* pw    = (const float*)d_in[5];
    const float* pb    = (const float*)d_in[6];

    int n = in_sizes[0] / FEAT;
    int e = in_sizes[1];
    if (n > MAXN) n = MAXN;
    if (e > MAXE) e = MAXE;

    static int smem_set = 0;
    if (!smem_set) {
        cudaFuncSetAttribute(gemm_mma_kernel,
                             cudaFuncAttributeMaxDynamicSharedMemorySize, GEMM_SMEM);
        smem_set = 1;
    }

    // fused setup: X/W fp16 convert + bucket scatter (g_cur pre-zeroed)
    setup_kernel<<<(n * FEAT + 255) / 256, 256>>>(feats, tw, pw, src, dst, n, e);

    int ntiles = (n + 95) / 96;
    int pgrid = ntiles < 148 ? ntiles : 148;   // persistent, 1 CTA/SM
    int warp_blocks = (n * 32 + 255) / 256;

    for (int l = 0; l < 4; l++) {
        gemm_mma_kernel<<<pgrid, 768, GEMM_SMEM>>>(l, tb + l * FEAT, pb + l * FEAT, n, ntiles);
        gather_kernel<<<warp_blocks, 256>>>((float*)d_out, l, n);
    }
}

// round 16
// speedup vs baseline: 1.0237x; 1.0237x over previous
#include <cuda_runtime.h>
#include <cuda_fp16.h>
#include <cstdint>
#include <float.h>

#define FEAT 128
#define MAXN 50000
#define MAXE 600000
#define CAP 96

// ---------------- scratch -------------------------------------------------
__device__ __half g_Ch[MAXN * FEAT];      // theta(x) fp16 (gather reads)
__device__ __half g_Dh[MAXN * FEAT];      // phi - theta + (tb+pb), fp16
__device__ __half g_Xf[MAXN * FEAT];      // current X, fp16
__device__ __half g_Wf[4 * 256 * 128];    // [l][row<128:theta else phi][k]
__device__ int g_cur[MAXN];   // bucket fill count == degree (zero-init at load;
                              // re-zeroed by gather layer 3 for the next run)
__device__ int g_csr[MAXN * CAP];         // premultiplied src*32, bucketed by dst

// ------- fused setup: convert X and W to fp16 + bucket scatter --------------
__global__ void setup_kernel(const float* __restrict__ x,
                             const float* __restrict__ tw,
                             const float* __restrict__ pw,
                             const int* __restrict__ src,
                             const int* __restrict__ dst,
                             int n, int e) {
    int i = blockIdx.x * blockDim.x + threadIdx.x;
    if (i < e) {
        int d = dst[i];
        int p = atomicAdd(&g_cur[d], 1);
        g_csr[d * CAP + p] = src[i] * 32;   // premultiplied uint2-row index
    }
    if (i < 4 * 256 * 128) {
        int l = i >> 15;
        int r = (i >> 7) & 255;
        int k = i & 127;
        const float* W = (r < 128) ? tw : pw;
        g_Wf[i] = __float2half_rn(W[(size_t)l * FEAT * FEAT + (size_t)(r & 127) * FEAT + k]);
    }
    if (i < n * FEAT) {
        g_Xf[i] = __float2half_rn(x[i]);
    }
}

// ------- persistent fp16 GEMM: B register-resident across tiles -------------
// BM=64, 512 threads, 16 warps = 2(m) x 4(n) x 2(theta/phi).
// Each warp: one 32x32 block (32 f32 acc) + B frags hoisted in 64 regs.
// Smem: W staged @0 (69632B) ONCE, then region reused:
//   A dbl buf [2][64 x 272B] @0/@17408, epi exchange 8x4KB @34816.
#define WROW 272
#define SM_A_BYTES (64 * WROW)
#define SM_EPI_OFF (2 * SM_A_BYTES)
#define GEMM_SMEM (256 * WROW)

__device__ __forceinline__ uint32_t smem_u32(const void* p) {
    uint32_t a;
    asm("{ .reg .u64 t; cvta.to.shared.u64 t, %1; cvt.u32.u64 %0, t; }" : "=r"(a) : "l"(p));
    return a;
}
__device__ __forceinline__ uint64_t gmem_u64(const void* p) {
    uint64_t a;
    asm("cvta.to.global.u64 %0, %1;" : "=l"(a) : "l"(p));
    return a;
}
#define CP_ASYNC16(dst, src, sz)                                             \
    asm volatile("cp.async.cg.shared.global [%0], [%1], 16, %2;"             \
                 :: "r"(dst), "l"(src), "r"(sz) : "memory")
#define CP_COMMIT() asm volatile("cp.async.commit_group;" ::: "memory")
#define CP_WAIT0() asm volatile("cp.async.wait_group 0;" ::: "memory")

#define LDMX4(r0, r1, r2, r3, addr)                                          \
    asm volatile("ldmatrix.sync.aligned.m8n8.x4.shared.b16 {%0,%1,%2,%3}, [%4];" \
                 : "=r"(r0), "=r"(r1), "=r"(r2), "=r"(r3) : "r"(addr))
#define MMA16816F(d, a0, a1, a2, a3, b0, b1)                                 \
    asm volatile("mma.sync.aligned.m16n8k16.row.col.f32.f16.f16.f32 "        \
                 "{%0,%1,%2,%3},{%4,%5,%6,%7},{%8,%9},{%0,%1,%2,%3};"        \
                 : "+f"((d)[0]), "+f"((d)[1]), "+f"((d)[2]), "+f"((d)[3])    \
                 : "r"(a0), "r"(a1), "r"(a2), "r"(a3), "r"(b0), "r"(b1))

__global__ void __launch_bounds__(512, 1)
gemm_mma_kernel(int layer, const float* __restrict__ tb,
                const float* __restrict__ pb, int n, int ntiles) {
    extern __shared__ __half sm[];
    uint32_t smb = smem_u32(sm);
    int t = threadIdx.x, lane = t & 31, wid = t >> 5;

    uint64_t Wg = gmem_u64(g_Wf + (size_t)layer * 32768);
    uint64_t Xg = gmem_u64(g_Xf);

    int tp     = wid & 1;          // 0 = theta, 1 = phi
    int warp_n = (wid >> 1) & 3;   // 4 n-warps x 32 cols
    int warp_m = wid >> 3;         // 2 m-warps x 32 rows
    int pair   = wid >> 1;         // theta/phi pair id (0..7) per (m,n)

    // ldmatrix lane maps
    int lr  = (lane & 7) + ((lane >> 3) & 1) * 8;
    int lk8 = (lane >> 4) * 8;
    int bg  = lane >> 3;
    int br_ = (lane & 7) + ((bg >> 1) & 1) * 8;
    int bk8 = (bg & 1) * 8;

    // ---- stage W into smem once (4096 x 16B, 8 chunks/thread) ----
    #pragma unroll
    for (int j = 0; j < 8; j++) {
        int i = t + j * 512;
        int row = i >> 4, q = i & 15;
        CP_ASYNC16(smb + (uint32_t)(row * WROW + q * 16),
                   Wg + (uint64_t)(row * 256 + q * 16), 16u);
    }
    CP_COMMIT();
    CP_WAIT0();
    __syncthreads();

    // ---- extract this warp's B fragments into registers (once) ----
    int brow_base = tp * 128 + warp_n * 32;
    uint32_t bFr[8][4][2];
    #pragma unroll
    for (int ks = 0; ks < 8; ks++) {
        int k = ks * 16;
        #pragma unroll
        for (int nh = 0; nh < 2; nh++) {
            uint32_t bd = smb + (uint32_t)((brow_base + nh * 16 + br_) * WROW + (k + bk8) * 2);
            LDMX4(bFr[ks][nh * 2][0], bFr[ks][nh * 2][1],
                  bFr[ks][nh * 2 + 1][0], bFr[ks][nh * 2 + 1][1], bd);
        }
    }
    __syncthreads();   // W region now dead; safe to reuse for A + epi

    // A loader: 64 rows x 16 chunks = 1024 x 16B, 2 per thread
    auto issue_A = [&](int tile, int buf) {
        int m0 = tile * 64;
        uint32_t stA = smb + (uint32_t)buf * SM_A_BYTES;
        #pragma unroll
        for (int j = 0; j < 2; j++) {
            int i = t + j * 512;
            int row = i >> 4, q = i & 15;
            int gr = m0 + row;
            uint32_t ok = (gr < n) ? 16u : 0u;
            CP_ASYNC16(stA + (uint32_t)(row * WROW + q * 16),
                       Xg + ((uint64_t)(uint32_t)gr * 256 + q * 16), ok);
        }
        CP_COMMIT();
    };

    int tile = blockIdx.x;
    if (tile < ntiles) issue_A(tile, 0);

    int buf = 0;
    for (; tile < ntiles; tile += gridDim.x, buf ^= 1) {
        int m0 = tile * 64;

        CP_WAIT0();
        __syncthreads();

        int ntile = tile + gridDim.x;
        if (ntile < ntiles) issue_A(ntile, buf ^ 1);

        float acc[2][4][4];
        #pragma unroll
        for (int mt = 0; mt < 2; mt++)
            #pragma unroll
            for (int nt = 0; nt < 4; nt++)
                #pragma unroll
                for (int r = 0; r < 4; r++) acc[mt][nt][r] = 0.f;

        uint32_t stA = smb + (uint32_t)buf * SM_A_BYTES;

        #pragma unroll
        for (int ks = 0; ks < 8; ks++) {
            int k = ks * 16;
            uint32_t aF[2][4];
            #pragma unroll
            for (int mt = 0; mt < 2; mt++) {
                uint32_t ad = stA + (uint32_t)((warp_m * 32 + mt * 16 + lr) * WROW + (k + lk8) * 2);
                LDMX4(aF[mt][0], aF[mt][1], aF[mt][2], aF[mt][3], ad);
            }
            #pragma unroll
            for (int mt = 0; mt < 2; mt++)
                #pragma unroll
                for (int nt = 0; nt < 4; nt++)
                    MMA16816F(acc[mt][nt], aF[mt][0], aF[mt][1], aF[mt][2], aF[mt][3],
                              bFr[ks][nt][0], bFr[ks][nt][1]);
        }

        // ---- epilogue: phi warps stage acc through smem; theta warps emit --
        float* epi = (float*)((char*)sm + SM_EPI_OFF + pair * 4096);
        if (tp == 1) {
            #pragma unroll
            for (int mt = 0; mt < 2; mt++)
                #pragma unroll
                for (int nt = 0; nt < 4; nt++)
                    *(float4*)(epi + (mt * 4 + nt) * 128 + lane * 4) =
                        *(float4*)acc[mt][nt];
        }
        __syncthreads();
        if (tp == 0) {
            #pragma unroll
            for (int mt = 0; mt < 2; mt++) {
                #pragma unroll
                for (int nt = 0; nt < 4; nt++) {
                    float4 pv = *(float4*)(epi + (mt * 4 + nt) * 128 + lane * 4);
                    int f = warp_n * 32 + nt * 8 + (lane & 3) * 2;
                    float bias0 = __ldg(&tb[f]) + __ldg(&pb[f]);
                    float bias1 = __ldg(&tb[f + 1]) + __ldg(&pb[f + 1]);
                    int m = m0 + warp_m * 32 + mt * 16 + (lane >> 2);
                    float* c = acc[mt][nt];
                    if (m < n) {
                        *(__half2*)(g_Ch + (size_t)m * FEAT + f) = __floats2half2_rn(c[0], c[1]);
                        *(__half2*)(g_Dh + (size_t)m * FEAT + f) =
                            __floats2half2_rn(pv.x - c[0] + bias0, pv.y - c[1] + bias1);
                    }
                    if (m + 8 < n) {
                        *(__half2*)(g_Ch + (size_t)(m + 8) * FEAT + f) = __floats2half2_rn(c[2], c[3]);
                        *(__half2*)(g_Dh + (size_t)(m + 8) * FEAT + f) =
                            __floats2half2_rn(pv.z - c[2] + bias0, pv.w - c[3] + bias1);
                    }
                }
            }
        }
    }
}

// ---------------- gather-max: 1 warp/node, uint2, MLP=2 (R11 exact) --------
__device__ __forceinline__ uint32_t hmax2u(uint32_t x, uint32_t y) {
    __half2 r = __hmax2(*(__half2*)&x, *(__half2*)&y);
    return *(uint32_t*)&r;
}

__global__ void gather_kernel(float* __restrict__ dout, int layer, int n) {
    int gw = (blockIdx.x * blockDim.x + threadIdx.x) >> 5;
    int lane = threadIdx.x & 31;
    if (gw >= n) return;

    int deg = g_cur[gw];
    const int* lst = g_csr + gw * CAP;
    const uint2* C2 = (const uint2*)g_Ch;

    // hoisted D load (independent of edge loop)
    uint2 dv = __ldg(&((const uint2*)g_Dh)[(size_t)gw * 32 + lane]);

    const uint32_t NEG = 0xFBFFFBFFu;  // -65504 x2
    uint32_t a0 = NEG, a1 = NEG, b0 = NEG, b1 = NEG;

    int e = 0;
    for (; e + 1 < deg; e += 2) {
        int s0 = __ldg(&lst[e]);          // premultiplied src*32
        int s1 = __ldg(&lst[e + 1]);
        uint2 v0 = __ldg(&C2[(size_t)(uint32_t)(s0 + lane)]);
        uint2 v1 = __ldg(&C2[(size_t)(uint32_t)(s1 + lane)]);
        a0 = hmax2u(a0, v0.x); a1 = hmax2u(a1, v0.y);
        b0 = hmax2u(b0, v1.x); b1 = hmax2u(b1, v1.y);
    }
    if (e < deg) {
        int s0 = __ldg(&lst[e]);
        uint2 v0 = __ldg(&C2[(size_t)(uint32_t)(s0 + lane)]);
        a0 = hmax2u(a0, v0.x); a1 = hmax2u(a1, v0.y);
    }
    a0 = hmax2u(a0, b0);
    a1 = hmax2u(a1, b1);

    float2 m01 = __half22float2(*(__half2*)&a0);
    float2 m23 = __half22float2(*(__half2*)&a1);
    float2 d01 = __half22float2(*(__half2*)&dv.x);
    float2 d23 = __half22float2(*(__half2*)&dv.y);

    float4 o;
    o.x = fmaxf(0.f, d01.x + m01.x);
    o.y = fmaxf(0.f, d01.y + m01.y);
    o.z = fmaxf(0.f, d23.x + m23.x);
    o.w = fmaxf(0.f, d23.y + m23.y);

    if (layer == 3) {
        ((float4*)dout)[(size_t)gw * 32 + lane] = o;
        if (lane == 0) g_cur[gw] = 0;     // re-arm bucket counters for next run
    } else {
        __half2 p0 = __floats2half2_rn(o.x, o.y);
        __half2 p1 = __floats2half2_rn(o.z, o.w);
        uint2 xv;
        xv.x = *(uint32_t*)&p0;
        xv.y = *(uint32_t*)&p1;
        *(uint2*)(g_Xf + (size_t)gw * FEAT + lane * 4) = xv;
    }
}

// ---------------- launch ----------------------------------------------------
extern "C" void kernel_launch(void* const* d_in, const int* in_sizes, int n_in,
                              void* d_out, int out_size) {
    const float* feats = (const float*)d_in[0];
    const int*   src   = (const int*)d_in[1];
    const int*   dst   = (const int*)d_in[2];
    const float* tw    = (const float*)d_in[3];
    const float* tb    = (const float*)d_in[4];
    const float* pw    = (const float*)d_in[5];
    const float* pb    = (const float*)d_in[6];

    int n = in_sizes[0] / FEAT;
    int e = in_sizes[1];
    if (n > MAXN) n = MAXN;
    if (e > MAXE) e = MAXE;

    static int smem_set = 0;
    if (!smem_set) {
        cudaFuncSetAttribute(gemm_mma_kernel,
                             cudaFuncAttributeMaxDynamicSharedMemorySize, GEMM_SMEM);
        smem_set = 1;
    }

    // fused setup: X/W fp16 convert + bucket scatter (g_cur pre-zeroed)
    setup_kernel<<<(n * FEAT + 255) / 256, 256>>>(feats, tw, pw, src, dst, n, e);

    int ntiles = (n + 63) / 64;
    int pgrid = ntiles < 148 ? ntiles : 148;   // persistent, 1 CTA/SM
    int warp_blocks = (n * 32 + 255) / 256;

    for (int l = 0; l < 4; l++) {
        gemm_mma_kernel<<<pgrid, 512, GEMM_SMEM>>>(l, tb + l * FEAT, pb + l * FEAT, n, ntiles);
        gather_kernel<<<warp_blocks, 256>>>((float*)d_out, l, n);
    }
}